// round 1
// baseline (speedup 1.0000x reference)
#include <cuda_runtime.h>
#include <cstdint>

// VectorQuantizer on B200 (sm_100a).
// inputs:  d_in[0] = inputs  [8, 64, 32, 32, 32] fp32  (16777216 elems)
//          d_in[1] = codebook [512, 64] fp32            (32768 elems)
// output:  d_out fp32, layout = [ quantized 16777216 | loss 1 | indices 262144 ]

#define KCODES   512
#define DCH      64
#define CB_STRIDE 68              // padded row stride (floats); 68%32==4 -> breaks epilogue bank conflicts, 16B aligned
#define SPATIAL  32768            // 32*32*32
#define BATCH    8
#define NVEC     (BATCH * SPATIAL)        // 262144
#define Q_ELEMS  (BATCH * DCH * SPATIAL)  // 16777216
#define LOSS_OFF Q_ELEMS
#define IDX_OFF  (Q_ELEMS + 1)

#define GRID_MAIN 148
#define BLOCK_MAIN 512

// per-block loss partial sums (deterministic final reduction in a 2nd kernel)
__device__ double g_blocksums[GRID_MAIN];

__inline__ __device__ float warpReduceSum(float v) {
    #pragma unroll
    for (int o = 16; o > 0; o >>= 1) v += __shfl_down_sync(0xffffffffu, v, o);
    return v;
}

__global__ __launch_bounds__(BLOCK_MAIN, 1)
void vq_main(const float* __restrict__ in, const float* __restrict__ cb,
             float* __restrict__ out) {
    extern __shared__ float smem[];
    float* scb   = smem;                       // [KCODES][CB_STRIDE]
    float* ssc   = smem + KCODES * CB_STRIDE;  // [KCODES]  = sum(c^2) per code
    float* swarp = ssc + KCODES;               // [16] warp partial loss sums

    // ---- load codebook into SMEM (float4) ----
    const float4* cb4 = (const float4*)cb;
    for (int i = threadIdx.x; i < KCODES * (DCH / 4); i += blockDim.x) {
        int k  = i >> 4;
        int j4 = i & 15;
        float4 v = cb4[i];
        *(float4*)(scb + k * CB_STRIDE + j4 * 4) = v;
    }
    __syncthreads();

    // ---- per-code squared norms ----
    if (threadIdx.x < KCODES) {
        const float* c = scb + threadIdx.x * CB_STRIDE;
        float s = 0.0f;
        #pragma unroll
        for (int j = 0; j < DCH; j++) s = fmaf(c[j], c[j], s);
        ssc[threadIdx.x] = s;
    }
    __syncthreads();

    float threadLoss = 0.0f;

    // ---- grid-stride over vectors ----
    for (int v = blockIdx.x * blockDim.x + threadIdx.x; v < NVEC;
         v += gridDim.x * blockDim.x) {
        int b = v >> 15;          // v / SPATIAL
        int s = v & (SPATIAL - 1);

        const float* xin = in + (size_t)b * DCH * SPATIAL + s;

        // load the 64-channel vector into registers (coalesced across warp per channel)
        float x[DCH];
        #pragma unroll
        for (int j = 0; j < DCH; j++) x[j] = xin[(size_t)j * SPATIAL];

        float sx = 0.0f;
        #pragma unroll
        for (int j = 0; j < DCH; j++) sx = fmaf(x[j], x[j], sx);

        float best = 3.4e38f;
        int   bidx = 0;

        #pragma unroll 2
        for (int k = 0; k < KCODES; k++) {
            const float* c = scb + k * CB_STRIDE;
            float a0 = 0.0f, a1 = 0.0f, a2 = 0.0f, a3 = 0.0f;
            #pragma unroll
            for (int j = 0; j < DCH; j += 4) {
                a0 = fmaf(c[j + 0], x[j + 0], a0);
                a1 = fmaf(c[j + 1], x[j + 1], a1);
                a2 = fmaf(c[j + 2], x[j + 2], a2);
                a3 = fmaf(c[j + 3], x[j + 3], a3);
            }
            float dot = (a0 + a1) + (a2 + a3);
            // match reference op order: (sum_x2 + sum_c2) - 2*dot
            float d = (sx + ssc[k]) - 2.0f * dot;
            if (d < best) { best = d; bidx = k; }  // strict < -> first-min tie-break like argmin
        }

        // ---- epilogue: scatter quantized vector back, accumulate loss ----
        float* q = out + (size_t)b * DCH * SPATIAL + s;
        const float* c = scb + bidx * CB_STRIDE;
        float lsum = 0.0f;
        #pragma unroll
        for (int j = 0; j < DCH; j++) {
            float cv = c[j];
            q[(size_t)j * SPATIAL] = cv;
            float df = cv - x[j];
            lsum = fmaf(df, df, lsum);
        }
        out[IDX_OFF + v] = (float)bidx;
        threadLoss += lsum;
    }

    // ---- block loss reduction (deterministic) ----
    float wsum = warpReduceSum(threadLoss);
    int wid  = threadIdx.x >> 5;
    int lane = threadIdx.x & 31;
    if (lane == 0) swarp[wid] = wsum;
    __syncthreads();
    if (threadIdx.x == 0) {
        double t = 0.0;
        int nwarps = blockDim.x >> 5;
        for (int i = 0; i < nwarps; i++) t += (double)swarp[i];
        g_blocksums[blockIdx.x] = t;
    }
}

__global__ void vq_finalize(float* __restrict__ out) {
    if (threadIdx.x == 0 && blockIdx.x == 0) {
        double t = 0.0;
        for (int i = 0; i < GRID_MAIN; i++) t += g_blocksums[i];
        // vq_loss = mean((q-x)^2) + 0.25*mean((q-x)^2) = 1.25 * sum / Q_ELEMS
        out[LOSS_OFF] = (float)(1.25 * t / (double)Q_ELEMS);
    }
}

extern "C" void kernel_launch(void* const* d_in, const int* in_sizes, int n_in,
                              void* d_out, int out_size) {
    const float* in = (const float*)d_in[0];
    const float* cb = (const float*)d_in[1];
    float* out = (float*)d_out;

    const int smem_bytes = (KCODES * CB_STRIDE + KCODES + 32) * (int)sizeof(float);
    // host-side attribute set; not a stream op, safe under graph capture
    static bool attr_set = false;
    if (!attr_set) {
        cudaFuncSetAttribute(vq_main, cudaFuncAttributeMaxDynamicSharedMemorySize, smem_bytes);
        attr_set = true;
    }

    vq_main<<<GRID_MAIN, BLOCK_MAIN, smem_bytes>>>(in, cb, out);
    vq_finalize<<<1, 32>>>(out);
}

// round 4
// speedup vs baseline: 1.1992x; 1.1992x over previous
#include <cuda_runtime.h>
#include <cstdint>

// VectorQuantizer on B200 (sm_100a) — round 4: f32x2 inner loop, ssc-init bug fixed,
// dot accumulation order made bit-identical to the round-1 passing kernel.
// inputs:  d_in[0] = inputs  [8, 64, 32, 32, 32] fp32  (16777216 elems)
//          d_in[1] = codebook [512, 64] fp32            (32768 elems)
// output:  d_out fp32, layout = [ quantized 16777216 | loss 1 | indices 262144 ]

#define KCODES    512
#define DCH       64
#define NPAIR     (DCH / 2)       // 32 packed f32x2 pairs per vector
#define CB_STRIDE 68              // padded row stride (floats); 16B-aligned
#define SPATIAL   32768           // 32*32*32
#define BATCH     8
#define NVEC      (BATCH * SPATIAL)        // 262144
#define Q_ELEMS   (BATCH * DCH * SPATIAL)  // 16777216
#define LOSS_OFF  Q_ELEMS
#define IDX_OFF   (Q_ELEMS + 1)

#define BLOCK_MAIN 448
#define GRID_MAIN  148

typedef unsigned long long u64;

__device__ double g_blocksums[GRID_MAIN];

__device__ __forceinline__ u64 fma2(u64 a, u64 b, u64 c) {
    u64 d;
    asm("fma.rn.f32x2 %0, %1, %2, %3;" : "=l"(d) : "l"(a), "l"(b), "l"(c));
    return d;
}
__device__ __forceinline__ u64 pack2(float lo, float hi) {
    u64 d;
    asm("mov.b64 %0, {%1, %2};" : "=l"(d) : "f"(lo), "f"(hi));
    return d;
}
__device__ __forceinline__ void unpack2(u64 v, float& lo, float& hi) {
    asm("mov.b64 {%0, %1}, %2;" : "=f"(lo), "=f"(hi) : "l"(v));
}

__inline__ __device__ float warpReduceSum(float v) {
    #pragma unroll
    for (int o = 16; o > 0; o >>= 1) v += __shfl_down_sync(0xffffffffu, v, o);
    return v;
}

__global__ __launch_bounds__(BLOCK_MAIN, 1)
void vq_main(const float* __restrict__ in, const float* __restrict__ cb,
             float* __restrict__ out) {
    extern __shared__ float smem[];
    float* scb   = smem;                       // [KCODES][CB_STRIDE]
    float* ssc   = smem + KCODES * CB_STRIDE;  // [KCODES] sum(c^2)
    float* swarp = ssc + KCODES;               // warp partial loss sums

    // ---- load codebook into SMEM (float4) ----
    const float4* cb4 = (const float4*)cb;
    for (int i = threadIdx.x; i < KCODES * (DCH / 4); i += blockDim.x) {
        int k  = i >> 4;
        int j4 = i & 15;
        float4 v = cb4[i];
        *(float4*)(scb + k * CB_STRIDE + j4 * 4) = v;
    }
    __syncthreads();

    // ---- per-code squared norms: grid-stride so ALL 512 entries are written
    //      (round-3 bug: `if (tid < KCODES)` with 448 threads left 64 entries garbage)
    for (int k = threadIdx.x; k < KCODES; k += blockDim.x) {
        const float* c = scb + k * CB_STRIDE;
        float s = 0.0f;
        #pragma unroll
        for (int j = 0; j < DCH; j++) s = fmaf(c[j], c[j], s);
        ssc[k] = s;
    }
    __syncthreads();

    float threadLoss = 0.0f;

    for (int v = blockIdx.x * blockDim.x + threadIdx.x; v < NVEC;
         v += gridDim.x * blockDim.x) {
        int b = v >> 15;
        int s = v & (SPATIAL - 1);

        const float* xin = in + (size_t)b * DCH * SPATIAL + s;

        // load the 64-channel vector, packed into 32 f32x2 pairs
        u64 xp[NPAIR];
        #pragma unroll
        for (int p = 0; p < NPAIR; p++) {
            float lo = xin[(size_t)(2 * p)     * SPATIAL];
            float hi = xin[(size_t)(2 * p + 1) * SPATIAL];
            xp[p] = pack2(lo, hi);
        }

        // sx: sequential j=0..63 (bit-compat with round 1)
        float sx = 0.0f;
        #pragma unroll
        for (int p = 0; p < NPAIR; p++) {
            float x0, x1; unpack2(xp[p], x0, x1);
            sx = fmaf(x0, x0, sx);
            sx = fmaf(x1, x1, sx);
        }

        float best = 3.4e38f;
        int   bidx = 0;

        #pragma unroll 2
        for (int k = 0; k < KCODES; k++) {
            const u64* crow = (const u64*)(scb + (size_t)k * CB_STRIDE);
            // Two f32x2 accumulators reproduce round-1's 4-scalar-accumulator
            // pattern bit-exactly:
            //   acc0 = pairs p=0,2,4,...  -> lanes (j%4==0, j%4==1)  == round1 a0,a1
            //   acc1 = pairs p=1,3,5,...  -> lanes (j%4==2, j%4==3)  == round1 a2,a3
            u64 acc0 = 0ull, acc1 = 0ull;
            #pragma unroll
            for (int p = 0; p < NPAIR; p += 2) {
                ulonglong2 cA = *(const ulonglong2*)(crow + p);  // one LDS.128
                acc0 = fma2(xp[p + 0], cA.x, acc0);
                acc1 = fma2(xp[p + 1], cA.y, acc1);
            }
            float f0, f1, f2, f3;
            unpack2(acc0, f0, f1);
            unpack2(acc1, f2, f3);
            float dot = (f0 + f1) + (f2 + f3);     // == (a0+a1)+(a2+a3) of round 1
            float d = (sx + ssc[k]) - 2.0f * dot;  // EXACT round-1 formula
            if (d < best) { best = d; bidx = k; }
        }

        // ---- epilogue: scatter quantized vector, accumulate loss ----
        float* q = out + (size_t)b * DCH * SPATIAL + s;
        const float* c = scb + bidx * CB_STRIDE;
        float lsum = 0.0f;
        #pragma unroll
        for (int p = 0; p < NPAIR; p++) {
            float x0, x1; unpack2(xp[p], x0, x1);
            float c0 = c[2 * p], c1 = c[2 * p + 1];
            q[(size_t)(2 * p)     * SPATIAL] = c0;
            q[(size_t)(2 * p + 1) * SPATIAL] = c1;
            float d0 = c0 - x0;
            lsum = fmaf(d0, d0, lsum);
            float d1 = c1 - x1;
            lsum = fmaf(d1, d1, lsum);
        }
        out[IDX_OFF + v] = (float)bidx;
        threadLoss += lsum;
    }

    // ---- block loss reduction ----
    float wsum = warpReduceSum(threadLoss);
    int wid  = threadIdx.x >> 5;
    int lane = threadIdx.x & 31;
    if (lane == 0) swarp[wid] = wsum;
    __syncthreads();
    if (threadIdx.x == 0) {
        double t = 0.0;
        int nwarps = blockDim.x >> 5;
        for (int i = 0; i < nwarps; i++) t += (double)swarp[i];
        g_blocksums[blockIdx.x] = t;
    }
}

__global__ void vq_finalize(float* __restrict__ out) {
    if (threadIdx.x == 0 && blockIdx.x == 0) {
        double t = 0.0;
        for (int i = 0; i < GRID_MAIN; i++) t += g_blocksums[i];
        out[LOSS_OFF] = (float)(1.25 * t / (double)Q_ELEMS);
    }
}

extern "C" void kernel_launch(void* const* d_in, const int* in_sizes, int n_in,
                              void* d_out, int out_size) {
    const float* in = (const float*)d_in[0];
    const float* cb = (const float*)d_in[1];
    float* out = (float*)d_out;

    const int smem_bytes = (KCODES * CB_STRIDE + KCODES + 32) * (int)sizeof(float);
    static bool attr_set = false;
    if (!attr_set) {
        cudaFuncSetAttribute(vq_main, cudaFuncAttributeMaxDynamicSharedMemorySize, smem_bytes);
        attr_set = true;
    }

    vq_main<<<GRID_MAIN, BLOCK_MAIN, smem_bytes>>>(in, cb, out);
    vq_finalize<<<1, 32>>>(out);
}